// round 17
// baseline (speedup 1.0000x reference)
#include <cuda_runtime.h>
#include <cuda_fp16.h>
#include <cstdint>
#include <math.h>

#define HIDDEN   256
#define NCLS     104
#define DIN      106
#define GX       128
#define NT       13          // n-tiles of 8
#define NSLICE   16          // k-slices of 16 (K=256)
#define ROWS_B   64          // rows per block (4 m-tiles)
#define MAXG     4096

// ---------------- device scratch (no cudaMalloc allowed) ----------------
__device__ float g_readout[MAXG * NCLS];
// Pre-packed fp16 W fragments, direct-LDG layout: index (slice*NT + j)*32 + lane
//   WB01: uint4 {WgT.b0, WgT.b1, WgB.b0, WgB.b1}   (both gate streams)
//   WB2 : uint2 {Wt.b0,  Wt.b1}                    (transform stream)
__device__ uint4 WB01[NSLICE * NT * 32];
__device__ uint2 WB2 [NSLICE * NT * 32];

// ---------------- helpers ----------------
__device__ __forceinline__ unsigned packh(float a, float b) {
    __half2 t = __floats2half2_rn(a, b);
    return *reinterpret_cast<unsigned*>(&t);
}
__device__ __forceinline__ void mma16816(float c[4], const unsigned a[4],
                                         unsigned b0, unsigned b1) {
    asm volatile(
        "mma.sync.aligned.m16n8k16.row.col.f32.f16.f16.f32 "
        "{%0,%1,%2,%3}, {%4,%5,%6,%7}, {%8,%9}, {%0,%1,%2,%3};"
        : "+f"(c[0]), "+f"(c[1]), "+f"(c[2]), "+f"(c[3])
        : "r"(a[0]), "r"(a[1]), "r"(a[2]), "r"(a[3]), "r"(b0), "r"(b1));
}

// ---------------- prep kernels ----------------
__global__ void zero_readout_k(float* __restrict__ p, int n) {
    int i = blockIdx.x * blockDim.x + threadIdx.x;
    if (i < n) p[i] = 0.0f;
}

__global__ void prep_weights(const float* __restrict__ Wg,
                             const float* __restrict__ Wt) {
    int idx = blockIdx.x * blockDim.x + threadIdx.x;
    if (idx >= NSLICE * NT * 32) return;
    int lane = idx & 31;
    int rest = idx >> 5;
    int j = rest % NT;
    int s = rest / NT;
    int n = j * 8 + (lane >> 2);
    int kk = (lane & 3) * 2;
    int k0 = s * 16;
    const int koffs[4] = {kk, kk + 1, kk + 8, kk + 9};

    float gT[4], gB[4], tr[4];
#pragma unroll
    for (int q = 0; q < 4; q++) {
        int k = k0 + koffs[q];
        gT[q] = Wg[k * NCLS + n];
        gB[q] = Wg[(256 + k) * NCLS + n];
        tr[q] = Wt[k * NCLS + n];
    }
    WB01[idx] = make_uint4(packh(gT[0], gT[1]), packh(gT[2], gT[3]),
                           packh(gB[0], gB[1]), packh(gB[2], gB[3]));
    WB2[idx]  = make_uint2(packh(tr[0], tr[1]), packh(tr[2], tr[3]));
}

// ---------------- main fused kernel: direct-LDG, no smem pipeline ----------------
// smem (dynamic, 26880 B): [0, 26624) Snw float[64][104]; [26624, 26880) gid_s int[64]
extern "C" __global__ void __launch_bounds__(256, 2)
readout_mma(const float* __restrict__ init_ns,
            const float* __restrict__ fin_ns,
            const int*   __restrict__ gids,
            const float* __restrict__ bg,
            const float* __restrict__ bt,
            float*       __restrict__ readout,
            int N)
{
    extern __shared__ char smraw[];
    float* Snw   = (float*)smraw;
    int*   gid_s = (int*)(smraw + 26624);

    const int tid = threadIdx.x;
    const int n0  = blockIdx.x * ROWS_B;
    const int nvalid = min(ROWS_B, N - n0);

    if (tid < ROWS_B) gid_s[tid] = (tid < nvalid) ? gids[n0 + tid] : -1;

    // ---- identities: warp -> (m-tile, ntile half) ----
    const int w     = tid >> 5;
    const int lane  = tid & 31;
    const int mt    = w & 3;             // m-tile 0..3 (16 rows each)
    const int wset  = w >> 2;            // 0: ntiles 0-6, 1: ntiles 7-12
    const int jstart = wset * 7;
    const int jcount = wset ? 6 : 7;
    const int gid   = lane >> 2;
    const int tig   = lane & 3;

    float accg[7][4];
    float acct[7][4];
#pragma unroll
    for (int jj = 0; jj < 7; jj++)
#pragma unroll
        for (int q = 0; q < 4; q++) { accg[jj][q] = 0.f; acct[jj][q] = 0.f; }

    // ---- A row pointers for this thread's fragments ----
    const int r0 = mt * 16 + gid;
    const int r1 = r0 + 8;
    const bool v0 = r0 < nvalid;
    const bool v1 = r1 < nvalid;
    const float* pi0 = init_ns + (size_t)(n0 + r0) * HIDDEN + tig * 2;
    const float* pi1 = init_ns + (size_t)(n0 + r1) * HIDDEN + tig * 2;
    const float* pf0 = fin_ns  + (size_t)(n0 + r0) * HIDDEN + tig * 2;
    const float* pf1 = fin_ns  + (size_t)(n0 + r1) * HIDDEN + tig * 2;

    const float2 z2 = make_float2(0.f, 0.f);
    float2 bi[4], bf[4];                 // next-slice A buffer (software pipeline)

    auto loadA = [&](int s) {
        const int c = s * 16;
        bi[0] = v0 ? *(const float2*)(pi0 + c)     : z2;
        bi[1] = v1 ? *(const float2*)(pi1 + c)     : z2;
        bi[2] = v0 ? *(const float2*)(pi0 + c + 8) : z2;
        bi[3] = v1 ? *(const float2*)(pi1 + c + 8) : z2;
        bf[0] = v0 ? *(const float2*)(pf0 + c)     : z2;
        bf[1] = v1 ? *(const float2*)(pf1 + c)     : z2;
        bf[2] = v0 ? *(const float2*)(pf0 + c + 8) : z2;
        bf[3] = v1 ? *(const float2*)(pf1 + c + 8) : z2;
    };

    // ---- main loop: no smem, no barriers ----
    loadA(0);
    for (int s = 0; s < NSLICE; s++) {
        // pack current A fragments
        unsigned aI[4], aF[4];
#pragma unroll
        for (int q = 0; q < 4; q++) {
            aI[q] = packh(bi[q].x, bi[q].y);
            aF[q] = packh(bf[q].x, bf[q].y);
        }
        // prefetch next slice's A (DRAM latency covered by this slice's MMAs)
        if (s + 1 < NSLICE) loadA(s + 1);

        const uint4* wp01 = WB01 + (s * NT + jstart) * 32 + lane;
        const uint2* wp2  = WB2  + (s * NT + jstart) * 32 + lane;
#pragma unroll
        for (int jj = 0; jj < 7; jj++) {
            if (jj < jcount) {
                uint4 wa = __ldg(wp01 + jj * 32);
                uint2 wb = __ldg(wp2  + jj * 32);
                mma16816(accg[jj], aI, wa.x, wa.y);   // gate: init @ WgT
                mma16816(accg[jj], aF, wa.z, wa.w);   // gate: fin  @ WgB
                mma16816(acct[jj], aF, wb.x, wb.y);   // transform
            }
        }
    }

    // ---- epilogue: sigmoid(gate)*transform -> Snw ----
#pragma unroll
    for (int jj = 0; jj < 7; jj++) {
        if (jj < jcount) {
            const int j = jstart + jj;
            const int col = j * 8 + tig * 2;
            float bg0 = __ldg(&bg[col]), bg1 = __ldg(&bg[col + 1]);
            float bt0 = __ldg(&bt[col]), bt1 = __ldg(&bt[col + 1]);
            float v00 = (acct[jj][0] + bt0) / (1.f + __expf(-(accg[jj][0] + bg0)));
            float v01 = (acct[jj][1] + bt1) / (1.f + __expf(-(accg[jj][1] + bg1)));
            float v10 = (acct[jj][2] + bt0) / (1.f + __expf(-(accg[jj][2] + bg0)));
            float v11 = (acct[jj][3] + bt1) / (1.f + __expf(-(accg[jj][3] + bg1)));
            Snw[r0 * NCLS + col]     = v00;
            Snw[r0 * NCLS + col + 1] = v01;
            Snw[r1 * NCLS + col]     = v10;
            Snw[r1 * NCLS + col + 1] = v11;
        }
    }
    __syncthreads();

    // ---- sorted segmented reduction + atomic flush ----
    if (tid < NCLS) {
        float acc = 0.0f;
        int cur = -2;
        for (int r = 0; r < ROWS_B; r++) {
            int g = gid_s[r];
            if (g != cur) {
                if (cur >= 0) atomicAdd(&readout[cur * NCLS + tid], acc);
                acc = 0.0f;
                cur = g;
            }
            if (g >= 0) acc += Snw[r * NCLS + tid];
        }
        if (cur >= 0) atomicAdd(&readout[cur * NCLS + tid], acc);
    }
}

// ---------------- BN + MLP head (ILP-unrolled) ----------------
__global__ void readout_mlp(const float* __restrict__ readout,
                            const float* __restrict__ aux,
                            const float* __restrict__ gamma,
                            const float* __restrict__ beta,
                            const float* __restrict__ mean,
                            const float* __restrict__ var,
                            const float* __restrict__ W1,
                            const float* __restrict__ b1,
                            const float* __restrict__ W2,
                            const float* __restrict__ b2,
                            float* __restrict__ out)
{
    __shared__ float nrm[DIN];
    __shared__ float h[GX];
    const int g = blockIdx.x;
    const int t = threadIdx.x;   // 128 threads

    if (t < DIN) {
        float e = (t < NCLS) ? readout[g * NCLS + t] : aux[g * 2 + (t - NCLS)];
        nrm[t] = (e - mean[t]) * rsqrtf(var[t] + 1e-5f) * gamma[t] + beta[t];
    }
    __syncthreads();

    {
        float s0 = b1[t], s1 = 0.f, s2 = 0.f, s3 = 0.f;
#pragma unroll
        for (int k = 0; k < 104; k += 4) {
            s0 += nrm[k]     * W1[(k)     * GX + t];
            s1 += nrm[k + 1] * W1[(k + 1) * GX + t];
            s2 += nrm[k + 2] * W1[(k + 2) * GX + t];
            s3 += nrm[k + 3] * W1[(k + 3) * GX + t];
        }
        s0 += nrm[104] * W1[104 * GX + t];
        s1 += nrm[105] * W1[105 * GX + t];
        h[t] = fmaxf((s0 + s1) + (s2 + s3), 0.0f);
    }
    __syncthreads();

    if (t < NCLS) {
        float s0 = b2[t], s1 = 0.f, s2 = 0.f, s3 = 0.f;
#pragma unroll
        for (int k = 0; k < GX; k += 4) {
            s0 += h[k]     * W2[(k)     * NCLS + t];
            s1 += h[k + 1] * W2[(k + 1) * NCLS + t];
            s2 += h[k + 2] * W2[(k + 2) * NCLS + t];
            s3 += h[k + 3] * W2[(k + 3) * NCLS + t];
        }
        out[g * NCLS + t] = (s0 + s1) + (s2 + s3);
    }
}

// ---------------- launch ----------------
extern "C" void kernel_launch(void* const* d_in, const int* in_sizes, int n_in,
                              void* d_out, int out_size)
{
    const float* init_ns = (const float*)d_in[0];
    const float* fin_ns  = (const float*)d_in[1];
    const float* aux     = (const float*)d_in[2];
    const int*   gids    = (const int*)d_in[3];
    const float* Wg  = (const float*)d_in[5];
    const float* bg  = (const float*)d_in[6];
    const float* Wt  = (const float*)d_in[7];
    const float* bt  = (const float*)d_in[8];
    const float* gma = (const float*)d_in[9];
    const float* bta = (const float*)d_in[10];
    const float* mn  = (const float*)d_in[11];
    const float* vr  = (const float*)d_in[12];
    const float* W1  = (const float*)d_in[13];
    const float* b1  = (const float*)d_in[14];
    const float* W2  = (const float*)d_in[15];
    const float* b2  = (const float*)d_in[16];
    float* out = (float*)d_out;

    const int N = in_sizes[0] / HIDDEN;
    int G = in_sizes[2] / 2;
    if (G > MAXG) G = MAXG;

    float* readout_ptr = nullptr;
    cudaGetSymbolAddress((void**)&readout_ptr, g_readout);

    const int smem_bytes = 26880;
    cudaFuncSetAttribute(readout_mma, cudaFuncAttributeMaxDynamicSharedMemorySize,
                         smem_bytes);

    zero_readout_k<<<(G * NCLS + 255) / 256, 256>>>(readout_ptr, G * NCLS);

    const int wtotal = NSLICE * NT * 32;
    prep_weights<<<(wtotal + 255) / 256, 256>>>(Wg, Wt);

    const int blocks = (N + ROWS_B - 1) / ROWS_B;
    readout_mma<<<blocks, 256, smem_bytes>>>(init_ns, fin_ns, gids,
                                             bg, bt, readout_ptr, N);

    readout_mlp<<<G, GX>>>(readout_ptr, aux, gma, bta, mn, vr, W1, b1, W2, b2, out);
}